// round 13
// baseline (speedup 1.0000x reference)
#include <cuda_runtime.h>

// Problem constants
#define BB   4
#define CC   16
#define HH   64
#define WW   64
#define FF   32
#define K2   9

#define TILE_W   16     // pixels per block
#define THREADS  256    // 8 warps: (c-quarter 0..3) x (px-half 0..1)
#define XCOLS    20     // 18 halo cols padded to 20 (80B rows, 16B aligned)
#define NGRP     (CC * K2 + 1)   // +1 padding group for unconditional prefetch

// Repacked coefficients: [c][k][g][f] float4, one padding (k) group at the end
//   g=0: {n0,n1,n2,n3}   g=1: {n4,n5,d0,d1}   g=2: {d2,d3,0,0}
__device__ float4 g_coef4[NGRP * 3 * FF];

__device__ __forceinline__ float rcp_fast(float q) {
    float r; asm("rcp.approx.f32 %0, %1;" : "=f"(r) : "f"(q)); return r;
}

// ---------------------------------------------------------------------------
// Kernel 1: repack coefficients into [c][k][g][f] float4
// ---------------------------------------------------------------------------
__global__ void repack_coefs_kernel(const float* __restrict__ nums,
                                    const float* __restrict__ denoms) {
    int idx = blockIdx.x * blockDim.x + threadIdx.x;
    const int total = CC * K2 * 3 * FF;
    if (idx >= total) return;
    int f = idx & (FF - 1);
    int g = (idx >> 5) % 3;
    int k = (idx >> 5) / 3 % K2;
    int c = idx / (FF * 3 * K2);
    const float* np = nums   + (((f * CC + c) * K2) + k) * 6;
    const float* dp = denoms + (((f * CC + c) * K2) + k) * 4;
    float4 v;
    if (g == 0)      v = make_float4(np[0], np[1], np[2], np[3]);
    else if (g == 1) v = make_float4(np[4], np[5], dp[0], dp[1]);
    else             v = make_float4(dp[2], dp[3], 0.f, 0.f);
    g_coef4[idx] = v;
}

// ---------------------------------------------------------------------------
// Kernel 2: rational (Pade) conv.
//   grid  = (W/16, H, B) = (4, 64, 4) = 1024 blocks, 256 threads (8 warps)
//   lane = f. warp -> (c-quarter = warp>>1 : 4 channels, px-half = warp&1).
//   ~48 resident warps/SM for latency hiding.
//   10 fma-pipe ops per rational eval: P Horner (5) + w Horner (3) +
//   q = fma(|x|,|w|,1) (1) + acc fma (1). |x| precomputed per window.
//   4-way c reduction via smem, fixed order (deterministic).
// ---------------------------------------------------------------------------
__global__ __launch_bounds__(THREADS, 4)
void rational_conv_kernel(const float* __restrict__ x, float* __restrict__ out) {
    __shared__ __align__(16) float xs[CC][3][XCOLS];   // 3.75 KB
    __shared__ float red[3][2][32][9];                 // quarters 1..3, pad 9

    const int wbase = blockIdx.x * TILE_W;
    const int h     = blockIdx.y;
    const int b     = blockIdx.z;
    const int tid   = threadIdx.x;
    const int lane  = tid & 31;            // f
    const int warp  = tid >> 5;            // 0..7
    const int cq    = warp >> 1;           // c-quarter 0..3
    const int pxw   = warp & 1;            // px-half
    const int px0   = pxw * 8;

    // --- Load halo: 16 channels x 3 rows x 18 cols (wbase-1 .. wbase+16)
    for (int i = tid; i < CC * 3 * 18; i += THREADS) {
        int j  = i % 18;
        int r  = (i / 18) % 3;
        int c  = i / 54;
        int hh = h - 1 + r;
        int ww = wbase - 1 + j;
        float v = 0.0f;
        if (hh >= 0 && hh < HH && ww >= 0 && ww < WW)
            v = x[((b * CC + c) * HH + hh) * WW + ww];
        xs[c][r][j] = v;
    }
    __syncthreads();

    float acc[8];
    #pragma unroll
    for (int i = 0; i < 8; ++i) acc[i] = 0.0f;

    const int cstart = cq * 4;

    // Linear coefficient cursor; prime with (c=cstart, k=0)
    const float4* cp = g_coef4 + (cstart * K2) * 3 * FF + lane;
    float4 A  = __ldg(cp);
    float4 Bv = __ldg(cp + FF);
    float4 Cv = __ldg(cp + 2 * FF);

    #pragma unroll 1
    for (int cc = 0; cc < 4; ++cc) {
        #pragma unroll
        for (int a = 0; a < 3; ++a) {
            // 12-float register window via 3 broadcast LDS.128
            const float* xrow = &xs[cstart + cc][a][px0];
            float4 xA = *reinterpret_cast<const float4*>(xrow);
            float4 xB = *reinterpret_cast<const float4*>(xrow + 4);
            float4 xC = *reinterpret_cast<const float4*>(xrow + 8);
            const float xw[12] = {xA.x, xA.y, xA.z, xA.w,
                                  xB.x, xB.y, xB.z, xB.w,
                                  xC.x, xC.y, xC.z, xC.w};
            // precomputed absolute window: 12 abs serve 24 evals
            float xa[12];
            #pragma unroll
            for (int j = 0; j < 12; ++j) xa[j] = fabsf(xw[j]);

            #pragma unroll
            for (int bb = 0; bb < 3; ++bb) {
                // --- unconditional prefetch of next k-group (linear walk;
                //     the very last step reads the padding group, discarded)
                cp += 3 * FF;
                float4 An = __ldg(cp);
                float4 Bn = __ldg(cp + FF);
                float4 Cn = __ldg(cp + 2 * FF);

                const float n0 = A.x,  n1 = A.y,  n2 = A.z,  n3 = A.w;
                const float n4 = Bv.x, n5 = Bv.y, d0 = Bv.z, d1 = Bv.w;
                const float d2 = Cv.x, d3 = Cv.y;
                #pragma unroll
                for (int i = 0; i < 8; ++i) {
                    const float xv = xw[i + bb];
                    // P(x): Horner, 5 FMA
                    float p = fmaf(xv, n5, n4);
                    p = fmaf(xv, p, n3);
                    p = fmaf(xv, p, n2);
                    p = fmaf(xv, p, n1);
                    p = fmaf(xv, p, n0);
                    // w(x) = d0 + d1 x + d2 x^2 + d3 x^3: 3 FMA
                    float w = fmaf(xv, d3, d2);
                    w = fmaf(xv, w, d1);
                    w = fmaf(xv, w, d0);
                    // Q = 1 + |x*w| = fma(|x|, |w|, 1); |x| precomputed
                    const float q = fmaf(xa[i + bb], fabsf(w), 1.0f);
                    acc[i] = fmaf(p, rcp_fast(q), acc[i]);
                }
                A = An; Bv = Bn; Cv = Cn;
            }
        }
    }

    // --- 4-way c reduction via smem, fixed order (deterministic)
    if (cq != 0) {
        #pragma unroll
        for (int i = 0; i < 8; ++i) red[cq - 1][pxw][lane][i] = acc[i];
    }
    __syncthreads();
    if (cq == 0) {
        #pragma unroll
        for (int i = 0; i < 8; ++i)
            acc[i] = ((acc[i] + red[0][pxw][lane][i]) +
                      red[1][pxw][lane][i]) + red[2][pxw][lane][i];
        float* op = out + ((b * FF + lane) * HH + h) * WW + wbase + px0;
        *reinterpret_cast<float4*>(op)     = make_float4(acc[0], acc[1], acc[2], acc[3]);
        *reinterpret_cast<float4*>(op + 4) = make_float4(acc[4], acc[5], acc[6], acc[7]);
    }
}

// ---------------------------------------------------------------------------
// Launch
// ---------------------------------------------------------------------------
extern "C" void kernel_launch(void* const* d_in, const int* in_sizes, int n_in,
                              void* d_out, int out_size) {
    const float* x      = (const float*)d_in[0];   // (4,16,64,64)
    const float* nums   = (const float*)d_in[1];   // (32,16,3,3,6)
    const float* denoms = (const float*)d_in[2];   // (32,16,3,3,4)
    float* out = (float*)d_out;                    // (4,32,64,64)

    const int total = CC * K2 * 3 * FF;
    repack_coefs_kernel<<<(total + 255) / 256, 256>>>(nums, denoms);

    dim3 grid(WW / TILE_W, HH, BB);
    rational_conv_kernel<<<grid, THREADS>>>(x, out);
}